// round 6
// baseline (speedup 1.0000x reference)
#include <cuda_runtime.h>
#include <cuda_bf16.h>
#include <cstdint>

#define NN 100000
#define NE 1600000
#define FH 128
#define CC 64

// ---------------- scratch ----------------
__device__ float g_h[3ll * NN * FH];   // h1,h2,h3
__device__ float g_y[(long long)NN * FH];
__device__ float g_z[(long long)NN * CC];
__device__ float g_onorm[NN];
__device__ float g_inorm[NN];
__device__ int   g_indeg[NN];
__device__ int   g_outdeg[NN];
__device__ int   g_rs[NN + 1];
__device__ int   g_cur[NN];
__device__ int   g_perm[NE];

// ---------------- helpers ----------------
__device__ __forceinline__ uint32_t to_tf32(float x) {
    uint32_t y;
    asm("cvt.rna.tf32.f32 %0, %1;" : "=r"(y) : "f"(x));
    return y;
}
__device__ __forceinline__ float to_tf32f(float x) {
    return __uint_as_float(to_tf32(x));
}

__device__ __forceinline__ void mma_tf32(float* c, const uint32_t* a, uint32_t b0, uint32_t b1) {
    asm volatile(
        "mma.sync.aligned.m16n8k8.row.col.f32.tf32.tf32.f32 "
        "{%0,%1,%2,%3}, {%4,%5,%6,%7}, {%8,%9}, {%0,%1,%2,%3};"
        : "+f"(c[0]), "+f"(c[1]), "+f"(c[2]), "+f"(c[3])
        : "r"(a[0]), "r"(a[1]), "r"(a[2]), "r"(a[3]), "r"(b0), "r"(b1));
}

// ---------------- graph prep ----------------
__global__ void k_zero() {
    int i = blockIdx.x * blockDim.x + threadIdx.x;
    if (i < NN) { g_indeg[i] = 0; g_outdeg[i] = 0; }
}

__global__ void k_degree(const int* __restrict__ src, const int* __restrict__ dst) {
    int e = blockIdx.x * blockDim.x + threadIdx.x;
    if (e < NE) {
        atomicAdd(&g_outdeg[src[e]], 1);
        atomicAdd(&g_indeg[dst[e]], 1);
    }
}

// exclusive scan of indeg -> rs/cur, plus norms (fused)
__global__ __launch_bounds__(1024) void k_scan() {
    __shared__ int sums[1024];
    int tid = threadIdx.x;
    const int chunk = (NN + 1023) / 1024;
    int b = tid * chunk;
    int e = min(b + chunk, NN);
    int s = 0;
    for (int i = b; i < e; i++) {
        int id = g_indeg[i];
        int od = g_outdeg[i];
        s += id;
        g_inorm[i] = id > 0 ? rsqrtf((float)id) : 0.f;
        g_onorm[i] = od > 0 ? rsqrtf((float)od) : 0.f;
    }
    sums[tid] = s;
    __syncthreads();
    for (int off = 1; off < 1024; off <<= 1) {
        int v = (tid >= off) ? sums[tid - off] : 0;
        __syncthreads();
        sums[tid] += v;
        __syncthreads();
    }
    int run = (tid == 0) ? 0 : sums[tid - 1];
    for (int i = b; i < e; i++) {
        g_rs[i] = run;
        g_cur[i] = run;
        run += g_indeg[i];
    }
    if (tid == 1023) g_rs[NN] = run;
}

__global__ void k_build(const int* __restrict__ src, const int* __restrict__ dst) {
    int e = blockIdx.x * blockDim.x + threadIdx.x;
    if (e < NE) {
        int p = atomicAdd(&g_cur[dst[e]], 1);
        g_perm[p] = src[e];
    }
}

// ---------------- TF32 GEMM: Y[N,128] = (X .* onorm) @ W[128,128] ----------------
// R4 version (no register prefetch — that spilled and regressed in R5).
__global__ __launch_bounds__(256) void k_gemm_conv_tc(const float* __restrict__ X,
                                                      const float* __restrict__ W,
                                                      float* __restrict__ Y) {
    __shared__ float As[128][36];   // [m][k], stride%32=4 -> frag loads conflict-free
    __shared__ float Ws[32][136];   // [k][n], stride%32=8 -> frag loads conflict-free
    int tid = threadIdx.x;
    int warp = tid >> 5, lane = tid & 31;
    int gid = lane >> 2, tig = lane & 3;
    int row0 = blockIdx.x * 128;

    float acc[16][4];
#pragma unroll
    for (int i = 0; i < 16; i++)
#pragma unroll
        for (int j = 0; j < 4; j++) acc[i][j] = 0.f;

    for (int kc = 0; kc < 4; kc++) {
        int k0 = kc * 32;
#pragma unroll
        for (int i = tid; i < 1024; i += 256) {
            int m = i >> 3, kq = (i & 7) * 4;
            int r = row0 + m;
            float4 v = make_float4(0.f, 0.f, 0.f, 0.f);
            float on = 0.f;
            if (r < NN) { v = *(const float4*)&X[r * 128 + k0 + kq]; on = g_onorm[r]; }
            As[m][kq + 0] = to_tf32f(v.x * on);
            As[m][kq + 1] = to_tf32f(v.y * on);
            As[m][kq + 2] = to_tf32f(v.z * on);
            As[m][kq + 3] = to_tf32f(v.w * on);
        }
#pragma unroll
        for (int i = tid; i < 1024; i += 256) {
            int k = i >> 5, nq = (i & 31) * 4;
            float4 v = *(const float4*)&W[(k0 + k) * 128 + nq];
            Ws[k][nq + 0] = to_tf32f(v.x);
            Ws[k][nq + 1] = to_tf32f(v.y);
            Ws[k][nq + 2] = to_tf32f(v.z);
            Ws[k][nq + 3] = to_tf32f(v.w);
        }
        __syncthreads();
#pragma unroll
        for (int ks = 0; ks < 4; ks++) {
            int kk = ks * 8;
            uint32_t a[4];
            a[0] = __float_as_uint(As[warp * 16 + gid][kk + tig]);
            a[1] = __float_as_uint(As[warp * 16 + gid + 8][kk + tig]);
            a[2] = __float_as_uint(As[warp * 16 + gid][kk + tig + 4]);
            a[3] = __float_as_uint(As[warp * 16 + gid + 8][kk + tig + 4]);
#pragma unroll
            for (int nt = 0; nt < 16; nt++) {
                uint32_t b0 = __float_as_uint(Ws[kk + tig][nt * 8 + gid]);
                uint32_t b1 = __float_as_uint(Ws[kk + tig + 4][nt * 8 + gid]);
                mma_tf32(acc[nt], a, b0, b1);
            }
        }
        __syncthreads();
    }

    int r0 = row0 + warp * 16 + gid;
    int r1 = r0 + 8;
#pragma unroll
    for (int nt = 0; nt < 16; nt++) {
        int c = nt * 8 + tig * 2;
        if (r0 < NN) *(float2*)&Y[r0 * 128 + c] = make_float2(acc[nt][0], acc[nt][1]);
        if (r1 < NN) *(float2*)&Y[r1 * 128 + c] = make_float2(acc[nt][2], acc[nt][3]);
    }
}

// ---------------- TF32 GEMM: Z[N,64] = concat(h1,h2,h3) @ Wo[384,64] ----------------
__global__ __launch_bounds__(256) void k_gemm_z_tc(const float* __restrict__ Hc,
                                                   const float* __restrict__ Wo,
                                                   float* __restrict__ Z) {
    __shared__ float As[128][36];
    __shared__ float Ws[32][72];    // stride%32=8
    int tid = threadIdx.x;
    int warp = tid >> 5, lane = tid & 31;
    int gid = lane >> 2, tig = lane & 3;
    int row0 = blockIdx.x * 128;

    float acc[8][4];
#pragma unroll
    for (int i = 0; i < 8; i++)
#pragma unroll
        for (int j = 0; j < 4; j++) acc[i][j] = 0.f;

    for (int kc = 0; kc < 12; kc++) {
        int k0 = kc * 32;
        int layer = k0 >> 7;
        int cb = k0 & 127;
        const float* Xb = Hc + (long long)layer * NN * 128;
#pragma unroll
        for (int i = tid; i < 1024; i += 256) {
            int m = i >> 3, kq = (i & 7) * 4;
            int r = row0 + m;
            float4 v = make_float4(0.f, 0.f, 0.f, 0.f);
            if (r < NN) v = *(const float4*)&Xb[r * 128 + cb + kq];
            As[m][kq + 0] = to_tf32f(v.x);
            As[m][kq + 1] = to_tf32f(v.y);
            As[m][kq + 2] = to_tf32f(v.z);
            As[m][kq + 3] = to_tf32f(v.w);
        }
#pragma unroll
        for (int i = tid; i < 512; i += 256) {
            int k = i >> 4, nq = (i & 15) * 4;
            float4 v = *(const float4*)&Wo[(k0 + k) * 64 + nq];
            Ws[k][nq + 0] = to_tf32f(v.x);
            Ws[k][nq + 1] = to_tf32f(v.y);
            Ws[k][nq + 2] = to_tf32f(v.z);
            Ws[k][nq + 3] = to_tf32f(v.w);
        }
        __syncthreads();
#pragma unroll
        for (int ks = 0; ks < 4; ks++) {
            int kk = ks * 8;
            uint32_t a[4];
            a[0] = __float_as_uint(As[warp * 16 + gid][kk + tig]);
            a[1] = __float_as_uint(As[warp * 16 + gid + 8][kk + tig]);
            a[2] = __float_as_uint(As[warp * 16 + gid][kk + tig + 4]);
            a[3] = __float_as_uint(As[warp * 16 + gid + 8][kk + tig + 4]);
#pragma unroll
            for (int nt = 0; nt < 8; nt++) {
                uint32_t b0 = __float_as_uint(Ws[kk + tig][nt * 8 + gid]);
                uint32_t b1 = __float_as_uint(Ws[kk + tig + 4][nt * 8 + gid]);
                mma_tf32(acc[nt], a, b0, b1);
            }
        }
        __syncthreads();
    }

    int r0 = row0 + warp * 16 + gid;
    int r1 = r0 + 8;
#pragma unroll
    for (int nt = 0; nt < 8; nt++) {
        int c = nt * 8 + tig * 2;
        if (r0 < NN) *(float2*)&Z[r0 * 64 + c] = make_float2(acc[nt][0], acc[nt][1]);
        if (r1 < NN) *(float2*)&Z[r1 * 64 + c] = make_float2(acc[nt][2], acc[nt][3]);
    }
}

// ---------------- aggregation: warp per node, float4 lanes ----------------
__global__ __launch_bounds__(256) void k_agg(const float* __restrict__ Y,
                                             const float* __restrict__ b,
                                             float* __restrict__ Hout) {
    int v = (blockIdx.x * 256 + threadIdx.x) >> 5;
    if (v >= NN) return;
    int lane = threadIdx.x & 31;
    int col = lane * 4;
    int s = g_rs[v], e = g_rs[v + 1];
    float4 a0 = make_float4(0.f, 0.f, 0.f, 0.f), a1 = a0, a2 = a0, a3 = a0;
    int j = s;
    for (; j + 4 <= e; j += 4) {
        int s0 = __ldg(&g_perm[j]), s1 = __ldg(&g_perm[j + 1]);
        int s2 = __ldg(&g_perm[j + 2]), s3 = __ldg(&g_perm[j + 3]);
        float4 v0 = __ldg((const float4*)&Y[s0 * 128 + col]);
        float4 v1 = __ldg((const float4*)&Y[s1 * 128 + col]);
        float4 v2 = __ldg((const float4*)&Y[s2 * 128 + col]);
        float4 v3 = __ldg((const float4*)&Y[s3 * 128 + col]);
        a0.x += v0.x; a0.y += v0.y; a0.z += v0.z; a0.w += v0.w;
        a1.x += v1.x; a1.y += v1.y; a1.z += v1.z; a1.w += v1.w;
        a2.x += v2.x; a2.y += v2.y; a2.z += v2.z; a2.w += v2.w;
        a3.x += v3.x; a3.y += v3.y; a3.z += v3.z; a3.w += v3.w;
    }
    for (; j < e; j++) {
        float4 v0 = __ldg((const float4*)&Y[__ldg(&g_perm[j]) * 128 + col]);
        a0.x += v0.x; a0.y += v0.y; a0.z += v0.z; a0.w += v0.w;
    }
    float in = g_inorm[v];
    float4 bb = __ldg((const float4*)&b[col]);
    float4 r;
    r.x = fmaxf((a0.x + a1.x + a2.x + a3.x) * in + bb.x, 0.f);
    r.y = fmaxf((a0.y + a1.y + a2.y + a3.y) * in + bb.y, 0.f);
    r.z = fmaxf((a0.z + a1.z + a2.z + a3.z) * in + bb.z, 0.f);
    r.w = fmaxf((a0.w + a1.w + a2.w + a3.w) * in + bb.w, 0.f);
    *(float4*)&Hout[v * 128 + col] = r;
}

// ---------------- final: warp per node, float2 lanes ----------------
__global__ __launch_bounds__(256) void k_final(const float* __restrict__ bo,
                                               float* __restrict__ Out) {
    int v = (blockIdx.x * 256 + threadIdx.x) >> 5;
    if (v >= NN) return;
    int lane = threadIdx.x & 31;
    int col = lane * 2;
    int s = g_rs[v], e = g_rs[v + 1];
    float2 a0 = make_float2(0.f, 0.f), a1 = a0, a2 = a0, a3 = a0;
    int j = s;
    for (; j + 4 <= e; j += 4) {
        int s0 = __ldg(&g_perm[j]), s1 = __ldg(&g_perm[j + 1]);
        int s2 = __ldg(&g_perm[j + 2]), s3 = __ldg(&g_perm[j + 3]);
        float2 v0 = __ldg((const float2*)&g_z[s0 * 64 + col]);
        float2 v1 = __ldg((const float2*)&g_z[s1 * 64 + col]);
        float2 v2 = __ldg((const float2*)&g_z[s2 * 64 + col]);
        float2 v3 = __ldg((const float2*)&g_z[s3 * 64 + col]);
        a0.x += v0.x; a0.y += v0.y;
        a1.x += v1.x; a1.y += v1.y;
        a2.x += v2.x; a2.y += v2.y;
        a3.x += v3.x; a3.y += v3.y;
    }
    for (; j < e; j++) {
        float2 v0 = __ldg((const float2*)&g_z[__ldg(&g_perm[j]) * 64 + col]);
        a0.x += v0.x; a0.y += v0.y;
    }
    float2 bb = __ldg((const float2*)&bo[col]);
    Out[v * 64 + col + 0] = (a0.x + a1.x) + (a2.x + a3.x) + bb.x;
    Out[v * 64 + col + 1] = (a0.y + a1.y) + (a2.y + a3.y) + bb.y;
}

// ---------------- host ----------------
extern "C" void kernel_launch(void* const* d_in, const int* in_sizes, int n_in,
                              void* d_out, int out_size) {
    const float* feats = (const float*)d_in[0];
    const int*   src   = (const int*)d_in[1];
    const int*   dst   = (const int*)d_in[2];
    const float* W0    = (const float*)d_in[3];
    const float* b0    = (const float*)d_in[4];
    const float* W1    = (const float*)d_in[5];
    const float* b1    = (const float*)d_in[6];
    const float* W2    = (const float*)d_in[7];
    const float* b2    = (const float*)d_in[8];
    const float* Wo    = (const float*)d_in[9];
    const float* bo    = (const float*)d_in[10];
    float* out = (float*)d_out;

    void *p_h, *p_y, *p_z;
    cudaGetSymbolAddress(&p_h, g_h);
    cudaGetSymbolAddress(&p_y, g_y);
    cudaGetSymbolAddress(&p_z, g_z);
    float* hbuf = (float*)p_h;
    float* ybuf = (float*)p_y;
    float* zbuf = (float*)p_z;

    int eb = (NE + 255) / 256;
    k_zero<<<(NN + 255) / 256, 256>>>();
    k_degree<<<eb, 256>>>(src, dst);
    k_scan<<<1, 1024>>>();
    k_build<<<eb, 256>>>(src, dst);

    int gb = (NN + 127) / 128;
    int ab = (NN * 32 + 255) / 256;

    k_gemm_conv_tc<<<gb, 256>>>(feats, W0, ybuf);
    k_agg<<<ab, 256>>>(ybuf, b0, hbuf);
    k_gemm_conv_tc<<<gb, 256>>>(hbuf, W1, ybuf);
    k_agg<<<ab, 256>>>(ybuf, b1, hbuf + (long long)NN * 128);
    k_gemm_conv_tc<<<gb, 256>>>(hbuf + (long long)NN * 128, W2, ybuf);
    k_agg<<<ab, 256>>>(ybuf, b2, hbuf + 2ll * NN * 128);
    k_gemm_z_tc<<<gb, 256>>>(hbuf, Wo, zbuf);
    k_final<<<ab, 256>>>(bo, out);
}

// round 7
// speedup vs baseline: 1.3853x; 1.3853x over previous
#include <cuda_runtime.h>
#include <cuda_bf16.h>
#include <cstdint>

#define NN 100000
#define NE 1600000
#define FH 128
#define CC 64

// ---------------- scratch ----------------
__device__ float g_h[3ll * NN * FH];            // h1,h2,h3 (fp32)
__device__ __nv_bfloat162 g_y[(long long)NN * 64];  // Y packed bf16x2 (128 cols -> 64 pairs)
__device__ float g_z[(long long)NN * CC];
__device__ float g_onorm[NN];
__device__ float g_inorm[NN];
__device__ int   g_indeg[NN];
__device__ int   g_outdeg[NN];
__device__ int   g_rs[NN + 1];
__device__ int   g_cur[NN];
__device__ int   g_perm[NE];

// ---------------- helpers ----------------
__device__ __forceinline__ uint32_t to_tf32(float x) {
    uint32_t y;
    asm("cvt.rna.tf32.f32 %0, %1;" : "=r"(y) : "f"(x));
    return y;
}
__device__ __forceinline__ float to_tf32f(float x) {
    return __uint_as_float(to_tf32(x));
}

__device__ __forceinline__ void mma_tf32(float* c, const uint32_t* a, uint32_t b0, uint32_t b1) {
    asm volatile(
        "mma.sync.aligned.m16n8k8.row.col.f32.tf32.tf32.f32 "
        "{%0,%1,%2,%3}, {%4,%5,%6,%7}, {%8,%9}, {%0,%1,%2,%3};"
        : "+f"(c[0]), "+f"(c[1]), "+f"(c[2]), "+f"(c[3])
        : "r"(a[0]), "r"(a[1]), "r"(a[2]), "r"(a[3]), "r"(b0), "r"(b1));
}

// ---------------- graph prep (exact R4 configuration) ----------------
__global__ void k_degree(const int* __restrict__ src, const int* __restrict__ dst) {
    int e = blockIdx.x * blockDim.x + threadIdx.x;
    if (e < NE) {
        atomicAdd(&g_outdeg[src[e]], 1);
        atomicAdd(&g_indeg[dst[e]], 1);
    }
}

__global__ void k_norms() {
    int i = blockIdx.x * blockDim.x + threadIdx.x;
    if (i < NN) {
        int od = g_outdeg[i], id = g_indeg[i];
        g_onorm[i] = od > 0 ? rsqrtf((float)od) : 0.f;
        g_inorm[i] = id > 0 ? rsqrtf((float)id) : 0.f;
    }
}

__global__ __launch_bounds__(1024) void k_scan() {
    __shared__ int sums[1024];
    int tid = threadIdx.x;
    const int chunk = (NN + 1023) / 1024;
    int b = tid * chunk;
    int e = min(b + chunk, NN);
    int s = 0;
    for (int i = b; i < e; i++) s += g_indeg[i];
    sums[tid] = s;
    __syncthreads();
    for (int off = 1; off < 1024; off <<= 1) {
        int v = (tid >= off) ? sums[tid - off] : 0;
        __syncthreads();
        sums[tid] += v;
        __syncthreads();
    }
    int run = (tid == 0) ? 0 : sums[tid - 1];
    for (int i = b; i < e; i++) {
        g_rs[i] = run;
        g_cur[i] = run;
        run += g_indeg[i];
    }
    if (tid == 1023) g_rs[NN] = run;
}

__global__ void k_build(const int* __restrict__ src, const int* __restrict__ dst) {
    int e = blockIdx.x * blockDim.x + threadIdx.x;
    if (e < NE) {
        int p = atomicAdd(&g_cur[dst[e]], 1);
        g_perm[p] = src[e];
    }
}

// ---------------- TF32 GEMM: Ybf16[N,128] = (X .* onorm) @ W[128,128] ----------------
__global__ __launch_bounds__(256) void k_gemm_conv_tc(const float* __restrict__ X,
                                                      const float* __restrict__ W,
                                                      __nv_bfloat162* __restrict__ Y) {
    __shared__ float As[128][36];
    __shared__ float Ws[32][136];
    int tid = threadIdx.x;
    int warp = tid >> 5, lane = tid & 31;
    int gid = lane >> 2, tig = lane & 3;
    int row0 = blockIdx.x * 128;

    float acc[16][4];
#pragma unroll
    for (int i = 0; i < 16; i++)
#pragma unroll
        for (int j = 0; j < 4; j++) acc[i][j] = 0.f;

    for (int kc = 0; kc < 4; kc++) {
        int k0 = kc * 32;
#pragma unroll
        for (int i = tid; i < 1024; i += 256) {
            int m = i >> 3, kq = (i & 7) * 4;
            int r = row0 + m;
            float4 v = make_float4(0.f, 0.f, 0.f, 0.f);
            float on = 0.f;
            if (r < NN) { v = *(const float4*)&X[r * 128 + k0 + kq]; on = g_onorm[r]; }
            As[m][kq + 0] = to_tf32f(v.x * on);
            As[m][kq + 1] = to_tf32f(v.y * on);
            As[m][kq + 2] = to_tf32f(v.z * on);
            As[m][kq + 3] = to_tf32f(v.w * on);
        }
#pragma unroll
        for (int i = tid; i < 1024; i += 256) {
            int k = i >> 5, nq = (i & 31) * 4;
            float4 v = *(const float4*)&W[(k0 + k) * 128 + nq];
            Ws[k][nq + 0] = to_tf32f(v.x);
            Ws[k][nq + 1] = to_tf32f(v.y);
            Ws[k][nq + 2] = to_tf32f(v.z);
            Ws[k][nq + 3] = to_tf32f(v.w);
        }
        __syncthreads();
#pragma unroll
        for (int ks = 0; ks < 4; ks++) {
            int kk = ks * 8;
            uint32_t a[4];
            a[0] = __float_as_uint(As[warp * 16 + gid][kk + tig]);
            a[1] = __float_as_uint(As[warp * 16 + gid + 8][kk + tig]);
            a[2] = __float_as_uint(As[warp * 16 + gid][kk + tig + 4]);
            a[3] = __float_as_uint(As[warp * 16 + gid + 8][kk + tig + 4]);
#pragma unroll
            for (int nt = 0; nt < 16; nt++) {
                uint32_t b0 = __float_as_uint(Ws[kk + tig][nt * 8 + gid]);
                uint32_t b1 = __float_as_uint(Ws[kk + tig + 4][nt * 8 + gid]);
                mma_tf32(acc[nt], a, b0, b1);
            }
        }
        __syncthreads();
    }

    int r0 = row0 + warp * 16 + gid;
    int r1 = r0 + 8;
#pragma unroll
    for (int nt = 0; nt < 16; nt++) {
        int cp = (nt * 8 + tig * 2) >> 1;   // bf16x2 pair index (c is even)
        if (r0 < NN) Y[r0 * 64 + cp] = __float22bfloat162_rn(make_float2(acc[nt][0], acc[nt][1]));
        if (r1 < NN) Y[r1 * 64 + cp] = __float22bfloat162_rn(make_float2(acc[nt][2], acc[nt][3]));
    }
}

// ---------------- TF32 GEMM: Z[N,64] = concat(h1,h2,h3) @ Wo[384,64] (fp32 in/out) ----------------
__global__ __launch_bounds__(256) void k_gemm_z_tc(const float* __restrict__ Hc,
                                                   const float* __restrict__ Wo,
                                                   float* __restrict__ Z) {
    __shared__ float As[128][36];
    __shared__ float Ws[32][72];
    int tid = threadIdx.x;
    int warp = tid >> 5, lane = tid & 31;
    int gid = lane >> 2, tig = lane & 3;
    int row0 = blockIdx.x * 128;

    float acc[8][4];
#pragma unroll
    for (int i = 0; i < 8; i++)
#pragma unroll
        for (int j = 0; j < 4; j++) acc[i][j] = 0.f;

    for (int kc = 0; kc < 12; kc++) {
        int k0 = kc * 32;
        int layer = k0 >> 7;
        int cb = k0 & 127;
        const float* Xb = Hc + (long long)layer * NN * 128;
#pragma unroll
        for (int i = tid; i < 1024; i += 256) {
            int m = i >> 3, kq = (i & 7) * 4;
            int r = row0 + m;
            float4 v = make_float4(0.f, 0.f, 0.f, 0.f);
            if (r < NN) v = *(const float4*)&Xb[r * 128 + cb + kq];
            As[m][kq + 0] = to_tf32f(v.x);
            As[m][kq + 1] = to_tf32f(v.y);
            As[m][kq + 2] = to_tf32f(v.z);
            As[m][kq + 3] = to_tf32f(v.w);
        }
#pragma unroll
        for (int i = tid; i < 512; i += 256) {
            int k = i >> 4, nq = (i & 15) * 4;
            float4 v = *(const float4*)&Wo[(k0 + k) * 64 + nq];
            Ws[k][nq + 0] = to_tf32f(v.x);
            Ws[k][nq + 1] = to_tf32f(v.y);
            Ws[k][nq + 2] = to_tf32f(v.z);
            Ws[k][nq + 3] = to_tf32f(v.w);
        }
        __syncthreads();
#pragma unroll
        for (int ks = 0; ks < 4; ks++) {
            int kk = ks * 8;
            uint32_t a[4];
            a[0] = __float_as_uint(As[warp * 16 + gid][kk + tig]);
            a[1] = __float_as_uint(As[warp * 16 + gid + 8][kk + tig]);
            a[2] = __float_as_uint(As[warp * 16 + gid][kk + tig + 4]);
            a[3] = __float_as_uint(As[warp * 16 + gid + 8][kk + tig + 4]);
#pragma unroll
            for (int nt = 0; nt < 8; nt++) {
                uint32_t b0 = __float_as_uint(Ws[kk + tig][nt * 8 + gid]);
                uint32_t b1 = __float_as_uint(Ws[kk + tig + 4][nt * 8 + gid]);
                mma_tf32(acc[nt], a, b0, b1);
            }
        }
        __syncthreads();
    }

    int r0 = row0 + warp * 16 + gid;
    int r1 = r0 + 8;
#pragma unroll
    for (int nt = 0; nt < 8; nt++) {
        int c = nt * 8 + tig * 2;
        if (r0 < NN) *(float2*)&Z[r0 * 64 + c] = make_float2(acc[nt][0], acc[nt][1]);
        if (r1 < NN) *(float2*)&Z[r1 * 64 + c] = make_float2(acc[nt][2], acc[nt][3]);
    }
}

// ---------------- aggregation: warp per node, bf16x2 gather (8B/lane/edge), fp32 accum ----------------
__global__ __launch_bounds__(256) void k_agg(const __nv_bfloat162* __restrict__ Y,
                                             const float* __restrict__ b,
                                             float* __restrict__ Hout) {
    int v = (blockIdx.x * 256 + threadIdx.x) >> 5;
    if (v >= NN) return;
    int lane = threadIdx.x & 31;
    int col = lane * 4;                  // 4 fp32 columns = 2 bf16x2 pairs
    int pbase = lane * 2;                // pair index within row
    int s = g_rs[v], e = g_rs[v + 1];
    float4 a0 = make_float4(0.f, 0.f, 0.f, 0.f), a1 = a0, a2 = a0, a3 = a0;

    auto acc4 = [](float4& a, uint2 u) {
        __nv_bfloat162 p0 = *(__nv_bfloat162*)&u.x;
        __nv_bfloat162 p1 = *(__nv_bfloat162*)&u.y;
        float2 f0 = __bfloat1622float2(p0);
        float2 f1 = __bfloat1622float2(p1);
        a.x += f0.x; a.y += f0.y; a.z += f1.x; a.w += f1.y;
    };

    int j = s;
    for (; j + 4 <= e; j += 4) {
        int s0 = __ldg(&g_perm[j]), s1 = __ldg(&g_perm[j + 1]);
        int s2 = __ldg(&g_perm[j + 2]), s3 = __ldg(&g_perm[j + 3]);
        uint2 u0 = __ldg((const uint2*)&Y[s0 * 64 + pbase]);
        uint2 u1 = __ldg((const uint2*)&Y[s1 * 64 + pbase]);
        uint2 u2 = __ldg((const uint2*)&Y[s2 * 64 + pbase]);
        uint2 u3 = __ldg((const uint2*)&Y[s3 * 64 + pbase]);
        acc4(a0, u0); acc4(a1, u1); acc4(a2, u2); acc4(a3, u3);
    }
    for (; j < e; j++) {
        uint2 u0 = __ldg((const uint2*)&Y[__ldg(&g_perm[j]) * 64 + pbase]);
        acc4(a0, u0);
    }
    float in = g_inorm[v];
    float4 bb = __ldg((const float4*)&b[col]);
    float4 r;
    r.x = fmaxf((a0.x + a1.x + a2.x + a3.x) * in + bb.x, 0.f);
    r.y = fmaxf((a0.y + a1.y + a2.y + a3.y) * in + bb.y, 0.f);
    r.z = fmaxf((a0.z + a1.z + a2.z + a3.z) * in + bb.z, 0.f);
    r.w = fmaxf((a0.w + a1.w + a2.w + a3.w) * in + bb.w, 0.f);
    *(float4*)&Hout[v * 128 + col] = r;
}

// ---------------- final: warp per node, float2 lanes (fp32, unchanged) ----------------
__global__ __launch_bounds__(256) void k_final(const float* __restrict__ bo,
                                               float* __restrict__ Out) {
    int v = (blockIdx.x * 256 + threadIdx.x) >> 5;
    if (v >= NN) return;
    int lane = threadIdx.x & 31;
    int col = lane * 2;
    int s = g_rs[v], e = g_rs[v + 1];
    float2 a0 = make_float2(0.f, 0.f), a1 = a0, a2 = a0, a3 = a0;
    int j = s;
    for (; j + 4 <= e; j += 4) {
        int s0 = __ldg(&g_perm[j]), s1 = __ldg(&g_perm[j + 1]);
        int s2 = __ldg(&g_perm[j + 2]), s3 = __ldg(&g_perm[j + 3]);
        float2 v0 = __ldg((const float2*)&g_z[s0 * 64 + col]);
        float2 v1 = __ldg((const float2*)&g_z[s1 * 64 + col]);
        float2 v2 = __ldg((const float2*)&g_z[s2 * 64 + col]);
        float2 v3 = __ldg((const float2*)&g_z[s3 * 64 + col]);
        a0.x += v0.x; a0.y += v0.y;
        a1.x += v1.x; a1.y += v1.y;
        a2.x += v2.x; a2.y += v2.y;
        a3.x += v3.x; a3.y += v3.y;
    }
    for (; j < e; j++) {
        float2 v0 = __ldg((const float2*)&g_z[__ldg(&g_perm[j]) * 64 + col]);
        a0.x += v0.x; a0.y += v0.y;
    }
    float2 bb = __ldg((const float2*)&bo[col]);
    Out[v * 64 + col + 0] = (a0.x + a1.x) + (a2.x + a3.x) + bb.x;
    Out[v * 64 + col + 1] = (a0.y + a1.y) + (a2.y + a3.y) + bb.y;
}

// ---------------- host ----------------
extern "C" void kernel_launch(void* const* d_in, const int* in_sizes, int n_in,
                              void* d_out, int out_size) {
    const float* feats = (const float*)d_in[0];
    const int*   src   = (const int*)d_in[1];
    const int*   dst   = (const int*)d_in[2];
    const float* W0    = (const float*)d_in[3];
    const float* b0    = (const float*)d_in[4];
    const float* W1    = (const float*)d_in[5];
    const float* b1    = (const float*)d_in[6];
    const float* W2    = (const float*)d_in[7];
    const float* b2    = (const float*)d_in[8];
    const float* Wo    = (const float*)d_in[9];
    const float* bo    = (const float*)d_in[10];
    float* out = (float*)d_out;

    void *p_indeg, *p_outdeg, *p_h, *p_y, *p_z;
    cudaGetSymbolAddress(&p_indeg, g_indeg);
    cudaGetSymbolAddress(&p_outdeg, g_outdeg);
    cudaGetSymbolAddress(&p_h, g_h);
    cudaGetSymbolAddress(&p_y, g_y);
    cudaGetSymbolAddress(&p_z, g_z);
    float* hbuf = (float*)p_h;
    __nv_bfloat162* ybuf = (__nv_bfloat162*)p_y;
    float* zbuf = (float*)p_z;

    cudaMemsetAsync(p_indeg, 0, NN * sizeof(int));
    cudaMemsetAsync(p_outdeg, 0, NN * sizeof(int));

    int eb = (NE + 255) / 256;
    k_degree<<<eb, 256>>>(src, dst);
    k_norms<<<(NN + 255) / 256, 256>>>();
    k_scan<<<1, 1024>>>();
    k_build<<<eb, 256>>>(src, dst);

    int gb = (NN + 127) / 128;
    int ab = (NN * 32 + 255) / 256;

    k_gemm_conv_tc<<<gb, 256>>>(feats, W0, ybuf);
    k_agg<<<ab, 256>>>(ybuf, b0, hbuf);
    k_gemm_conv_tc<<<gb, 256>>>(hbuf, W1, ybuf);
    k_agg<<<ab, 256>>>(ybuf, b1, hbuf + (long long)NN * 128);
    k_gemm_conv_tc<<<gb, 256>>>(hbuf + 1ll * NN * 128, W2, ybuf);
    k_agg<<<ab, 256>>>(ybuf, b2, hbuf + 2ll * NN * 128);
    k_gemm_z_tc<<<gb, 256>>>(hbuf, Wo, zbuf);
    k_final<<<ab, 256>>>(bo, out);
}

// round 10
// speedup vs baseline: 1.4047x; 1.0140x over previous
#include <cuda_runtime.h>
#include <cuda_bf16.h>
#include <cstdint>

#define NN 100000
#define NE 1600000
#define FH 128
#define CC 64

// ---------------- scratch ----------------
__device__ float g_h[3ll * NN * FH];            // h1,h2,h3 (fp32)
__device__ __nv_bfloat162 g_y[(long long)NN * 64];  // Y packed bf16x2 (128 cols -> 64 pairs)
__device__ float g_z[(long long)NN * CC];
__device__ float g_onorm[NN];
__device__ float g_inorm[NN];
__device__ int   g_indeg[NN];
__device__ int   g_outdeg[NN];
__device__ int   g_rs[NN + 1];
__device__ int   g_cur[NN];
__device__ int   g_perm[NE];

// ---------------- helpers ----------------
__device__ __forceinline__ uint32_t to_tf32(float x) {
    uint32_t y;
    asm("cvt.rna.tf32.f32 %0, %1;" : "=r"(y) : "f"(x));
    return y;
}
__device__ __forceinline__ float to_tf32f(float x) {
    return __uint_as_float(to_tf32(x));
}

__device__ __forceinline__ void mma_tf32(float* c, const uint32_t* a, uint32_t b0, uint32_t b1) {
    asm volatile(
        "mma.sync.aligned.m16n8k8.row.col.f32.tf32.tf32.f32 "
        "{%0,%1,%2,%3}, {%4,%5,%6,%7}, {%8,%9}, {%0,%1,%2,%3};"
        : "+f"(c[0]), "+f"(c[1]), "+f"(c[2]), "+f"(c[3])
        : "r"(a[0]), "r"(a[1]), "r"(a[2]), "r"(a[3]), "r"(b0), "r"(b1));
}

// ---------------- graph prep ----------------
__global__ void k_degree(const int* __restrict__ src, const int* __restrict__ dst) {
    int e = blockIdx.x * blockDim.x + threadIdx.x;
    if (e < NE) {
        atomicAdd(&g_outdeg[src[e]], 1);
        atomicAdd(&g_indeg[dst[e]], 1);
    }
}

__global__ void k_norms() {
    int i = blockIdx.x * blockDim.x + threadIdx.x;
    if (i < NN) {
        int od = g_outdeg[i], id = g_indeg[i];
        g_onorm[i] = od > 0 ? rsqrtf((float)od) : 0.f;
        g_inorm[i] = id > 0 ? rsqrtf((float)id) : 0.f;
    }
}

__global__ __launch_bounds__(1024) void k_scan() {
    __shared__ int sums[1024];
    int tid = threadIdx.x;
    const int chunk = (NN + 1023) / 1024;
    int b = tid * chunk;
    int e = min(b + chunk, NN);
    int s = 0;
    for (int i = b; i < e; i++) s += g_indeg[i];
    sums[tid] = s;
    __syncthreads();
    for (int off = 1; off < 1024; off <<= 1) {
        int v = (tid >= off) ? sums[tid - off] : 0;
        __syncthreads();
        sums[tid] += v;
        __syncthreads();
    }
    int run = (tid == 0) ? 0 : sums[tid - 1];
    for (int i = b; i < e; i++) {
        g_rs[i] = run;
        g_cur[i] = run;
        run += g_indeg[i];
    }
    if (tid == 1023) g_rs[NN] = run;
}

__global__ void k_build(const int* __restrict__ src, const int* __restrict__ dst) {
    int e = blockIdx.x * blockDim.x + threadIdx.x;
    if (e < NE) {
        int p = atomicAdd(&g_cur[dst[e]], 1);
        g_perm[p] = src[e];
    }
}

// ---------------- TF32 GEMM: Ybf16[N,128] = (X .* onorm) @ W[128,128] ----------------
// M=64 x N=64 tiles (blockIdx.y = N-half), 256 thr / 8 warps, 18.4KB smem -> 2 blocks/SM.
// warp w: rows (w&3)*16..+16, cols (w>>2)*32..+32 within the half.
__global__ __launch_bounds__(256) void k_gemm_conv_tc(const float* __restrict__ X,
                                                      const float* __restrict__ W,
                                                      __nv_bfloat162* __restrict__ Y) {
    __shared__ float As[64][36];   // [m][k] pad: stride%32=4
    __shared__ float Ws[32][72];   // [k][n] pad: stride%32=8
    int tid = threadIdx.x;
    int warp = tid >> 5, lane = tid & 31;
    int gid = lane >> 2, tig = lane & 3;
    int m0 = (warp & 3) * 16;
    int ng = warp >> 2;            // 0 or 1 -> n offset 0/32
    int row0 = blockIdx.x * 64;
    int nh = blockIdx.y * 64;      // N-half offset in output cols

    float acc[4][4];
#pragma unroll
    for (int i = 0; i < 4; i++)
#pragma unroll
        for (int j = 0; j < 4; j++) acc[i][j] = 0.f;

    for (int kc = 0; kc < 4; kc++) {
        int k0 = kc * 32;
        // stage A: 64x32 floats = 512 float4, 2 per thread
#pragma unroll
        for (int u = 0; u < 2; u++) {
            int i = tid + u * 256;
            int m = i >> 3, kq = (i & 7) * 4;
            int r = row0 + m;
            float4 v = make_float4(0.f, 0.f, 0.f, 0.f);
            float on = 0.f;
            if (r < NN) { v = *(const float4*)&X[r * 128 + k0 + kq]; on = g_onorm[r]; }
            As[m][kq + 0] = to_tf32f(v.x * on);
            As[m][kq + 1] = to_tf32f(v.y * on);
            As[m][kq + 2] = to_tf32f(v.z * on);
            As[m][kq + 3] = to_tf32f(v.w * on);
        }
        // stage W: 32x64 floats = 512 float4, 2 per thread
#pragma unroll
        for (int u = 0; u < 2; u++) {
            int i = tid + u * 256;
            int k = i >> 4, nq = (i & 15) * 4;
            float4 v = *(const float4*)&W[(k0 + k) * 128 + nh + nq];
            Ws[k][nq + 0] = to_tf32f(v.x);
            Ws[k][nq + 1] = to_tf32f(v.y);
            Ws[k][nq + 2] = to_tf32f(v.z);
            Ws[k][nq + 3] = to_tf32f(v.w);
        }
        __syncthreads();
#pragma unroll
        for (int ks = 0; ks < 4; ks++) {
            int kk = ks * 8;
            uint32_t a[4];
            a[0] = __float_as_uint(As[m0 + gid][kk + tig]);
            a[1] = __float_as_uint(As[m0 + gid + 8][kk + tig]);
            a[2] = __float_as_uint(As[m0 + gid][kk + tig + 4]);
            a[3] = __float_as_uint(As[m0 + gid + 8][kk + tig + 4]);
#pragma unroll
            for (int nt = 0; nt < 4; nt++) {
                uint32_t b0 = __float_as_uint(Ws[kk + tig][ng * 32 + nt * 8 + gid]);
                uint32_t b1 = __float_as_uint(Ws[kk + tig + 4][ng * 32 + nt * 8 + gid]);
                mma_tf32(acc[nt], a, b0, b1);
            }
        }
        __syncthreads();
    }

    int r0 = row0 + m0 + gid;
    int r1 = r0 + 8;
#pragma unroll
    for (int nt = 0; nt < 4; nt++) {
        int cp = (nh + ng * 32 + nt * 8 + tig * 2) >> 1;   // bf16x2 pair index
        if (r0 < NN) Y[r0 * 64 + cp] = __float22bfloat162_rn(make_float2(acc[nt][0], acc[nt][1]));
        if (r1 < NN) Y[r1 * 64 + cp] = __float22bfloat162_rn(make_float2(acc[nt][2], acc[nt][3]));
    }
}

// ---------------- TF32 GEMM: Z[N,64] = concat(h1,h2,h3) @ Wo[384,64] ----------------
// M=64 x N=64 (full), same tiling. 12 k-chunks across 3 layer slices.
__global__ __launch_bounds__(256) void k_gemm_z_tc(const float* __restrict__ Hc,
                                                   const float* __restrict__ Wo,
                                                   float* __restrict__ Z) {
    __shared__ float As[64][36];
    __shared__ float Ws[32][72];
    int tid = threadIdx.x;
    int warp = tid >> 5, lane = tid & 31;
    int gid = lane >> 2, tig = lane & 3;
    int m0 = (warp & 3) * 16;
    int ng = warp >> 2;
    int row0 = blockIdx.x * 64;

    float acc[4][4];
#pragma unroll
    for (int i = 0; i < 4; i++)
#pragma unroll
        for (int j = 0; j < 4; j++) acc[i][j] = 0.f;

    for (int kc = 0; kc < 12; kc++) {
        int k0 = kc * 32;
        const float* Xb = Hc + (long long)(k0 >> 7) * NN * 128;
        int cb = k0 & 127;
#pragma unroll
        for (int u = 0; u < 2; u++) {
            int i = tid + u * 256;
            int m = i >> 3, kq = (i & 7) * 4;
            int r = row0 + m;
            float4 v = make_float4(0.f, 0.f, 0.f, 0.f);
            if (r < NN) v = *(const float4*)&Xb[r * 128 + cb + kq];
            As[m][kq + 0] = to_tf32f(v.x);
            As[m][kq + 1] = to_tf32f(v.y);
            As[m][kq + 2] = to_tf32f(v.z);
            As[m][kq + 3] = to_tf32f(v.w);
        }
#pragma unroll
        for (int u = 0; u < 2; u++) {
            int i = tid + u * 256;
            int k = i >> 4, nq = (i & 15) * 4;
            float4 v = *(const float4*)&Wo[(k0 + k) * 64 + nq];
            Ws[k][nq + 0] = to_tf32f(v.x);
            Ws[k][nq + 1] = to_tf32f(v.y);
            Ws[k][nq + 2] = to_tf32f(v.z);
            Ws[k][nq + 3] = to_tf32f(v.w);
        }
        __syncthreads();
#pragma unroll
        for (int ks = 0; ks < 4; ks++) {
            int kk = ks * 8;
            uint32_t a[4];
            a[0] = __float_as_uint(As[m0 + gid][kk + tig]);
            a[1] = __float_as_uint(As[m0 + gid + 8][kk + tig]);
            a[2] = __float_as_uint(As[m0 + gid][kk + tig + 4]);
            a[3] = __float_as_uint(As[m0 + gid + 8][kk + tig + 4]);
#pragma unroll
            for (int nt = 0; nt < 4; nt++) {
                uint32_t b0 = __float_as_uint(Ws[kk + tig][ng * 32 + nt * 8 + gid]);
                uint32_t b1 = __float_as_uint(Ws[kk + tig + 4][ng * 32 + nt * 8 + gid]);
                mma_tf32(acc[nt], a, b0, b1);
            }
        }
        __syncthreads();
    }

    int r0 = row0 + m0 + gid;
    int r1 = r0 + 8;
#pragma unroll
    for (int nt = 0; nt < 4; nt++) {
        int c = ng * 32 + nt * 8 + tig * 2;
        if (r0 < NN) *(float2*)&Z[r0 * 64 + c] = make_float2(acc[nt][0], acc[nt][1]);
        if (r1 < NN) *(float2*)&Z[r1 * 64 + c] = make_float2(acc[nt][2], acc[nt][3]);
    }
}

// ---------------- aggregation: warp per node, bf16x2 gather, fp32 accum ----------------
__global__ __launch_bounds__(256) void k_agg(const __nv_bfloat162* __restrict__ Y,
                                             const float* __restrict__ b,
                                             float* __restrict__ Hout) {
    int v = (blockIdx.x * 256 + threadIdx.x) >> 5;
    if (v >= NN) return;
    int lane = threadIdx.x & 31;
    int col = lane * 4;
    int pbase = lane * 2;
    int s = g_rs[v], e = g_rs[v + 1];
    float4 a0 = make_float4(0.f, 0.f, 0.f, 0.f), a1 = a0, a2 = a0, a3 = a0;

    auto acc4 = [](float4& a, uint2 u) {
        __nv_bfloat162 p0 = *(__nv_bfloat162*)&u.x;
        __nv_bfloat162 p1 = *(__nv_bfloat162*)&u.y;
        float2 f0 = __bfloat1622float2(p0);
        float2 f1 = __bfloat1622float2(p1);
        a.x += f0.x; a.y += f0.y; a.z += f1.x; a.w += f1.y;
    };

    int j = s;
    for (; j + 4 <= e; j += 4) {
        int s0 = __ldg(&g_perm[j]), s1 = __ldg(&g_perm[j + 1]);
        int s2 = __ldg(&g_perm[j + 2]), s3 = __ldg(&g_perm[j + 3]);
        uint2 u0 = __ldg((const uint2*)&Y[s0 * 64 + pbase]);
        uint2 u1 = __ldg((const uint2*)&Y[s1 * 64 + pbase]);
        uint2 u2 = __ldg((const uint2*)&Y[s2 * 64 + pbase]);
        uint2 u3 = __ldg((const uint2*)&Y[s3 * 64 + pbase]);
        acc4(a0, u0); acc4(a1, u1); acc4(a2, u2); acc4(a3, u3);
    }
    for (; j < e; j++) {
        uint2 u0 = __ldg((const uint2*)&Y[__ldg(&g_perm[j]) * 64 + pbase]);
        acc4(a0, u0);
    }
    float in = g_inorm[v];
    float4 bb = __ldg((const float4*)&b[col]);
    float4 r;
    r.x = fmaxf((a0.x + a1.x + a2.x + a3.x) * in + bb.x, 0.f);
    r.y = fmaxf((a0.y + a1.y + a2.y + a3.y) * in + bb.y, 0.f);
    r.z = fmaxf((a0.z + a1.z + a2.z + a3.z) * in + bb.z, 0.f);
    r.w = fmaxf((a0.w + a1.w + a2.w + a3.w) * in + bb.w, 0.f);
    *(float4*)&Hout[v * 128 + col] = r;
}

// ---------------- final: warp per node, float2 lanes ----------------
__global__ __launch_bounds__(256) void k_final(const float* __restrict__ bo,
                                               float* __restrict__ Out) {
    int v = (blockIdx.x * 256 + threadIdx.x) >> 5;
    if (v >= NN) return;
    int lane = threadIdx.x & 31;
    int col = lane * 2;
    int s = g_rs[v], e = g_rs[v + 1];
    float2 a0 = make_float2(0.f, 0.f), a1 = a0, a2 = a0, a3 = a0;
    int j = s;
    for (; j + 4 <= e; j += 4) {
        int s0 = __ldg(&g_perm[j]), s1 = __ldg(&g_perm[j + 1]);
        int s2 = __ldg(&g_perm[j + 2]), s3 = __ldg(&g_perm[j + 3]);
        float2 v0 = __ldg((const float2*)&g_z[s0 * 64 + col]);
        float2 v1 = __ldg((const float2*)&g_z[s1 * 64 + col]);
        float2 v2 = __ldg((const float2*)&g_z[s2 * 64 + col]);
        float2 v3 = __ldg((const float2*)&g_z[s3 * 64 + col]);
        a0.x += v0.x; a0.y += v0.y;
        a1.x += v1.x; a1.y += v1.y;
        a2.x += v2.x; a2.y += v2.y;
        a3.x += v3.x; a3.y += v3.y;
    }
    for (; j < e; j++) {
        float2 v0 = __ldg((const float2*)&g_z[__ldg(&g_perm[j]) * 64 + col]);
        a0.x += v0.x; a0.y += v0.y;
    }
    float2 bb = __ldg((const float2*)&bo[col]);
    Out[v * 64 + col + 0] = (a0.x + a1.x) + (a2.x + a3.x) + bb.x;
    Out[v * 64 + col + 1] = (a0.y + a1.y) + (a2.y + a3.y) + bb.y;
}

// ---------------- host ----------------
extern "C" void kernel_launch(void* const* d_in, const int* in_sizes, int n_in,
                              void* d_out, int out_size) {
    const float* feats = (const float*)d_in[0];
    const int*   src   = (const int*)d_in[1];
    const int*   dst   = (const int*)d_in[2];
    const float* W0    = (const float*)d_in[3];
    const float* b0    = (const float*)d_in[4];
    const float* W1    = (const float*)d_in[5];
    const float* b1    = (const float*)d_in[6];
    const float* W2    = (const float*)d_in[7];
    const float* b2    = (const float*)d_in[8];
    const float* Wo    = (const float*)d_in[9];
    const float* bo    = (const float*)d_in[10];
    float* out = (float*)d_out;

    void *p_indeg, *p_outdeg, *p_h, *p_y, *p_z;
    cudaGetSymbolAddress(&p_indeg, g_indeg);
    cudaGetSymbolAddress(&p_outdeg, g_outdeg);
    cudaGetSymbolAddress(&p_h, g_h);
    cudaGetSymbolAddress(&p_y, g_y);
    cudaGetSymbolAddress(&p_z, g_z);
    float* hbuf = (float*)p_h;
    __nv_bfloat162* ybuf = (__nv_bfloat162*)p_y;
    float* zbuf = (float*)p_z;

    cudaMemsetAsync(p_indeg, 0, NN * sizeof(int));
    cudaMemsetAsync(p_outdeg, 0, NN * sizeof(int));

    int eb = (NE + 255) / 256;
    k_degree<<<eb, 256>>>(src, dst);
    k_norms<<<(NN + 255) / 256, 256>>>();
    k_scan<<<1, 1024>>>();
    k_build<<<eb, 256>>>(src, dst);

    dim3 gconv((NN + 63) / 64, 2);       // M-tiles x N-halves
    int gz = (NN + 63) / 64;
    int ab = (NN * 32 + 255) / 256;

    k_gemm_conv_tc<<<gconv, 256>>>(feats, W0, ybuf);
    k_agg<<<ab, 256>>>(ybuf, b0, hbuf);
    k_gemm_conv_tc<<<gconv, 256>>>(hbuf, W1, ybuf);
    k_agg<<<ab, 256>>>(ybuf, b1, hbuf + (long long)NN * 128);
    k_gemm_conv_tc<<<gconv, 256>>>(hbuf + 1ll * NN * 128, W2, ybuf);
    k_agg<<<ab, 256>>>(ybuf, b2, hbuf + 2ll * NN * 128);
    k_gemm_z_tc<<<gz, 256>>>(hbuf, Wo, zbuf);
    k_final<<<ab, 256>>>(bo, out);
}

// round 11
// speedup vs baseline: 1.5819x; 1.1261x over previous
#include <cuda_runtime.h>
#include <cuda_bf16.h>
#include <cstdint>

#define NN 100000
#define NE 1600000
#define FH 128
#define CC 64
#define GB1 3126          // gemm blocks in fused kernel: ceil(NN/64)*2
#define DEGB 6250         // degree blocks: ceil(NE/256)

// ---------------- scratch ----------------
__device__ float g_h[3ll * NN * FH];                 // h1,h2,h3 (fp32)
__device__ __nv_bfloat162 g_y[(long long)NN * 64];   // Y packed bf16x2
__device__ float g_z[(long long)NN * CC];
__device__ __align__(16) float g_onorm[NN];
__device__ __align__(16) float g_inorm[NN];
__device__ __align__(16) int   g_indeg[NN];
__device__ __align__(16) int   g_outdeg[NN];
__device__ __align__(16) int   g_rs[NN + 4];
__device__ __align__(16) int   g_cur[NN + 4];
__device__ int   g_perm[NE];

// ---------------- helpers ----------------
__device__ __forceinline__ uint32_t to_tf32(float x) {
    uint32_t y;
    asm("cvt.rna.tf32.f32 %0, %1;" : "=r"(y) : "f"(x));
    return y;
}
__device__ __forceinline__ float to_tf32f(float x) {
    return __uint_as_float(to_tf32(x));
}

__device__ __forceinline__ void mma_tf32(float* c, const uint32_t* a, uint32_t b0, uint32_t b1) {
    asm volatile(
        "mma.sync.aligned.m16n8k8.row.col.f32.tf32.tf32.f32 "
        "{%0,%1,%2,%3}, {%4,%5,%6,%7}, {%8,%9}, {%0,%1,%2,%3};"
        : "+f"(c[0]), "+f"(c[1]), "+f"(c[2]), "+f"(c[3])
        : "r"(a[0]), "r"(a[1]), "r"(a[2]), "r"(a[3]), "r"(b0), "r"(b1));
}

// ---------------- TF32 conv GEMM body: Yraw[N,128] = X @ W[128,128]  (NO onorm) ----------------
// M=64 x N=64 tile (by = N-half). 256 thr / 8 warps. Register-prefetch pipeline (acc=16 regs -> no spill).
__device__ __forceinline__ void gemm_conv_body(const float* __restrict__ X,
                                               const float* __restrict__ W,
                                               __nv_bfloat162* __restrict__ Y,
                                               int bx, int by) {
    __shared__ float As[64][36];   // [m][k] pad: stride%32=4
    __shared__ float Ws[32][72];   // [k][n] pad: stride%32=8
    int tid = threadIdx.x;
    int warp = tid >> 5, lane = tid & 31;
    int gid = lane >> 2, tig = lane & 3;
    int m0 = (warp & 3) * 16;
    int ng = warp >> 2;
    int row0 = bx * 64;
    int nh = by * 64;

    float acc[4][4];
#pragma unroll
    for (int i = 0; i < 4; i++)
#pragma unroll
        for (int j = 0; j < 4; j++) acc[i][j] = 0.f;

    float4 pa[2], pw[2];

    auto ldA = [&](int k0) {
#pragma unroll
        for (int u = 0; u < 2; u++) {
            int i = tid + u * 256;
            int m = i >> 3, kq = (i & 7) * 4;
            int r = row0 + m;
            pa[u] = (r < NN) ? *(const float4*)&X[r * 128 + k0 + kq]
                             : make_float4(0.f, 0.f, 0.f, 0.f);
        }
    };
    auto ldW = [&](int k0) {
#pragma unroll
        for (int u = 0; u < 2; u++) {
            int i = tid + u * 256;
            int k = i >> 4, nq = (i & 15) * 4;
            pw[u] = *(const float4*)&W[(k0 + k) * 128 + nh + nq];
        }
    };
    auto stAW = [&]() {
#pragma unroll
        for (int u = 0; u < 2; u++) {
            int i = tid + u * 256;
            int m = i >> 3, kq = (i & 7) * 4;
            As[m][kq + 0] = to_tf32f(pa[u].x);
            As[m][kq + 1] = to_tf32f(pa[u].y);
            As[m][kq + 2] = to_tf32f(pa[u].z);
            As[m][kq + 3] = to_tf32f(pa[u].w);
            int k = i >> 4, nq = (i & 15) * 4;
            Ws[k][nq + 0] = to_tf32f(pw[u].x);
            Ws[k][nq + 1] = to_tf32f(pw[u].y);
            Ws[k][nq + 2] = to_tf32f(pw[u].z);
            Ws[k][nq + 3] = to_tf32f(pw[u].w);
        }
    };

    ldA(0); ldW(0);
    stAW();
    __syncthreads();

    for (int kc = 0; kc < 4; kc++) {
        if (kc < 3) { ldA((kc + 1) * 32); ldW((kc + 1) * 32); }   // prefetch next chunk
#pragma unroll
        for (int ks = 0; ks < 4; ks++) {
            int kk = ks * 8;
            uint32_t a[4];
            a[0] = __float_as_uint(As[m0 + gid][kk + tig]);
            a[1] = __float_as_uint(As[m0 + gid + 8][kk + tig]);
            a[2] = __float_as_uint(As[m0 + gid][kk + tig + 4]);
            a[3] = __float_as_uint(As[m0 + gid + 8][kk + tig + 4]);
#pragma unroll
            for (int nt = 0; nt < 4; nt++) {
                uint32_t b0 = __float_as_uint(Ws[kk + tig][ng * 32 + nt * 8 + gid]);
                uint32_t b1 = __float_as_uint(Ws[kk + tig + 4][ng * 32 + nt * 8 + gid]);
                mma_tf32(acc[nt], a, b0, b1);
            }
        }
        __syncthreads();
        if (kc < 3) {
            stAW();
            __syncthreads();
        }
    }

    int r0 = row0 + m0 + gid;
    int r1 = r0 + 8;
#pragma unroll
    for (int nt = 0; nt < 4; nt++) {
        int cp = (nh + ng * 32 + nt * 8 + tig * 2) >> 1;
        if (r0 < NN) Y[r0 * 64 + cp] = __float22bfloat162_rn(make_float2(acc[nt][0], acc[nt][1]));
        if (r1 < NN) Y[r1 * 64 + cp] = __float22bfloat162_rn(make_float2(acc[nt][2], acc[nt][3]));
    }
}

// ---------------- fused: layer-1 GEMM + degree counting (independent work, one launch) ----------------
__global__ __launch_bounds__(256) void k_fused1(const int* __restrict__ src,
                                                const int* __restrict__ dst,
                                                const float* __restrict__ X,
                                                const float* __restrict__ W,
                                                __nv_bfloat162* __restrict__ Y) {
    if (blockIdx.x < GB1) {
        gemm_conv_body(X, W, Y, blockIdx.x >> 1, blockIdx.x & 1);
    } else {
        int e = (blockIdx.x - GB1) * 256 + threadIdx.x;
        if (e < NE) {
            atomicAdd(&g_outdeg[src[e]], 1);
            atomicAdd(&g_indeg[dst[e]], 1);
        }
    }
}

// ---------------- plain conv GEMM (layers 2,3) ----------------
__global__ __launch_bounds__(256) void k_gemm_conv_tc(const float* __restrict__ X,
                                                      const float* __restrict__ W,
                                                      __nv_bfloat162* __restrict__ Y) {
    gemm_conv_body(X, W, Y, blockIdx.x, blockIdx.y);
}

// ---------------- scan + norms (int4, fused) ----------------
__global__ __launch_bounds__(1024) void k_scan() {
    __shared__ int sums[1024];
    int tid = threadIdx.x;
    const int chunk = 100;               // threads 0..999 active, 25 int4 each
    int b = tid * chunk;
    int s = 0;
    if (b < NN) {
        const int4* p = (const int4*)(g_indeg + b);
#pragma unroll 5
        for (int i = 0; i < 25; i++) {
            int4 v = p[i];
            s += v.x + v.y + v.z + v.w;
        }
    }
    sums[tid] = s;
    __syncthreads();
    for (int off = 1; off < 1024; off <<= 1) {
        int v = (tid >= off) ? sums[tid - off] : 0;
        __syncthreads();
        sums[tid] += v;
        __syncthreads();
    }
    int run = (tid == 0) ? 0 : sums[tid - 1];
    if (b < NN) {
        const int4* pi = (const int4*)(g_indeg + b);
        const int4* po = (const int4*)(g_outdeg + b);
        for (int i = 0; i < 25; i++) {
            int4 di = pi[i];
            int4 dq = po[i];
            int4 r4;
            r4.x = run; run += di.x;
            r4.y = run; run += di.y;
            r4.z = run; run += di.z;
            r4.w = run; run += di.w;
            *(int4*)(g_rs + b + i * 4) = r4;
            *(int4*)(g_cur + b + i * 4) = r4;
            float4 in4, on4;
            in4.x = di.x > 0 ? rsqrtf((float)di.x) : 0.f;
            in4.y = di.y > 0 ? rsqrtf((float)di.y) : 0.f;
            in4.z = di.z > 0 ? rsqrtf((float)di.z) : 0.f;
            in4.w = di.w > 0 ? rsqrtf((float)di.w) : 0.f;
            on4.x = dq.x > 0 ? rsqrtf((float)dq.x) : 0.f;
            on4.y = dq.y > 0 ? rsqrtf((float)dq.y) : 0.f;
            on4.z = dq.z > 0 ? rsqrtf((float)dq.z) : 0.f;
            on4.w = dq.w > 0 ? rsqrtf((float)dq.w) : 0.f;
            *(float4*)(g_inorm + b + i * 4) = in4;
            *(float4*)(g_onorm + b + i * 4) = on4;
        }
        if (b + chunk == NN) g_rs[NN] = run;
    }
}

__global__ void k_build(const int* __restrict__ src, const int* __restrict__ dst) {
    int e = blockIdx.x * blockDim.x + threadIdx.x;
    if (e < NE) {
        int p = atomicAdd(&g_cur[dst[e]], 1);
        g_perm[p] = src[e];
    }
}

// ---------------- TF32 GEMM: Z[N,64] = concat(h1,h2,h3) @ Wo[384,64] (pipelined) ----------------
__global__ __launch_bounds__(256) void k_gemm_z_tc(const float* __restrict__ Hc,
                                                   const float* __restrict__ Wo,
                                                   float* __restrict__ Z) {
    __shared__ float As[64][36];
    __shared__ float Ws[32][72];
    int tid = threadIdx.x;
    int warp = tid >> 5, lane = tid & 31;
    int gid = lane >> 2, tig = lane & 3;
    int m0 = (warp & 3) * 16;
    int ng = warp >> 2;
    int row0 = blockIdx.x * 64;

    float acc[4][4];
#pragma unroll
    for (int i = 0; i < 4; i++)
#pragma unroll
        for (int j = 0; j < 4; j++) acc[i][j] = 0.f;

    float4 pa[2], pw[2];

    auto ldA = [&](int kc) {
        int k0 = kc * 32;
        const float* Xb = Hc + (long long)(k0 >> 7) * NN * 128;
        int cb = k0 & 127;
#pragma unroll
        for (int u = 0; u < 2; u++) {
            int i = tid + u * 256;
            int m = i >> 3, kq = (i & 7) * 4;
            int r = row0 + m;
            pa[u] = (r < NN) ? *(const float4*)&Xb[r * 128 + cb + kq]
                             : make_float4(0.f, 0.f, 0.f, 0.f);
        }
    };
    auto ldW = [&](int kc) {
        int k0 = kc * 32;
#pragma unroll
        for (int u = 0; u < 2; u++) {
            int i = tid + u * 256;
            int k = i >> 4, nq = (i & 15) * 4;
            pw[u] = *(const float4*)&Wo[(k0 + k) * 64 + nq];
        }
    };
    auto stAW = [&]() {
#pragma unroll
        for (int u = 0; u < 2; u++) {
            int i = tid + u * 256;
            int m = i >> 3, kq = (i & 7) * 4;
            As[m][kq + 0] = to_tf32f(pa[u].x);
            As[m][kq + 1] = to_tf32f(pa[u].y);
            As[m][kq + 2] = to_tf32f(pa[u].z);
            As[m][kq + 3] = to_tf32f(pa[u].w);
            int k = i >> 4, nq = (i & 15) * 4;
            Ws[k][nq + 0] = to_tf32f(pw[u].x);
            Ws[k][nq + 1] = to_tf32f(pw[u].y);
            Ws[k][nq + 2] = to_tf32f(pw[u].z);
            Ws[k][nq + 3] = to_tf32f(pw[u].w);
        }
    };

    ldA(0); ldW(0);
    stAW();
    __syncthreads();

    for (int kc = 0; kc < 12; kc++) {
        if (kc < 11) { ldA(kc + 1); ldW(kc + 1); }
#pragma unroll
        for (int ks = 0; ks < 4; ks++) {
            int kk = ks * 8;
            uint32_t a[4];
            a[0] = __float_as_uint(As[m0 + gid][kk + tig]);
            a[1] = __float_as_uint(As[m0 + gid + 8][kk + tig]);
            a[2] = __float_as_uint(As[m0 + gid][kk + tig + 4]);
            a[3] = __float_as_uint(As[m0 + gid + 8][kk + tig + 4]);
#pragma unroll
            for (int nt = 0; nt < 4; nt++) {
                uint32_t b0 = __float_as_uint(Ws[kk + tig][ng * 32 + nt * 8 + gid]);
                uint32_t b1 = __float_as_uint(Ws[kk + tig + 4][ng * 32 + nt * 8 + gid]);
                mma_tf32(acc[nt], a, b0, b1);
            }
        }
        __syncthreads();
        if (kc < 11) {
            stAW();
            __syncthreads();
        }
    }

    int r0 = row0 + m0 + gid;
    int r1 = r0 + 8;
#pragma unroll
    for (int nt = 0; nt < 4; nt++) {
        int c = ng * 32 + nt * 8 + tig * 2;
        if (r0 < NN) *(float2*)&Z[r0 * 64 + c] = make_float2(acc[nt][0], acc[nt][1]);
        if (r1 < NN) *(float2*)&Z[r1 * 64 + c] = make_float2(acc[nt][2], acc[nt][3]);
    }
}

// ---------------- aggregation: warp per node, bf16x2 gather, per-edge onorm, fp32 accum ----------------
__global__ __launch_bounds__(256) void k_agg(const __nv_bfloat162* __restrict__ Y,
                                             const float* __restrict__ b,
                                             float* __restrict__ Hout) {
    int v = (blockIdx.x * 256 + threadIdx.x) >> 5;
    if (v >= NN) return;
    int lane = threadIdx.x & 31;
    int col = lane * 4;
    int pbase = lane * 2;
    int s = g_rs[v], e = g_rs[v + 1];
    float4 a0 = make_float4(0.f, 0.f, 0.f, 0.f), a1 = a0, a2 = a0, a3 = a0;

    auto acc4 = [](float4& a, uint2 u, float on) {
        __nv_bfloat162 p0 = *(__nv_bfloat162*)&u.x;
        __nv_bfloat162 p1 = *(__nv_bfloat162*)&u.y;
        float2 f0 = __bfloat1622float2(p0);
        float2 f1 = __bfloat1622float2(p1);
        a.x += on * f0.x; a.y += on * f0.y; a.z += on * f1.x; a.w += on * f1.y;
    };

    int j = s;
    for (; j + 4 <= e; j += 4) {
        int s0 = __ldg(&g_perm[j]), s1 = __ldg(&g_perm[j + 1]);
        int s2 = __ldg(&g_perm[j + 2]), s3 = __ldg(&g_perm[j + 3]);
        float on0 = __ldg(&g_onorm[s0]), on1 = __ldg(&g_onorm[s1]);
        float on2 = __ldg(&g_onorm[s2]), on3 = __ldg(&g_onorm[s3]);
        uint2 u0 = __ldg((const uint2*)&Y[s0 * 64 + pbase]);
        uint2 u1 = __ldg((const uint2*)&Y[s1 * 64 + pbase]);
        uint2 u2 = __ldg((const uint2*)&Y[s2 * 64 + pbase]);
        uint2 u3 = __ldg((const uint2*)&Y[s3 * 64 + pbase]);
        acc4(a0, u0, on0); acc4(a1, u1, on1); acc4(a2, u2, on2); acc4(a3, u3, on3);
    }
    for (; j < e; j++) {
        int s0 = __ldg(&g_perm[j]);
        float on0 = __ldg(&g_onorm[s0]);
        uint2 u0 = __ldg((const uint2*)&Y[s0 * 64 + pbase]);
        acc4(a0, u0, on0);
    }
    float in = g_inorm[v];
    float4 bb = __ldg((const float4*)&b[col]);
    float4 r;
    r.x = fmaxf((a0.x + a1.x + a2.x + a3.x) * in + bb.x, 0.f);
    r.y = fmaxf((a0.y + a1.y + a2.y + a3.y) * in + bb.y, 0.f);
    r.z = fmaxf((a0.z + a1.z + a2.z + a3.z) * in + bb.z, 0.f);
    r.w = fmaxf((a0.w + a1.w + a2.w + a3.w) * in + bb.w, 0.f);
    *(float4*)&Hout[v * 128 + col] = r;
}

// ---------------- final: warp per node, float2 lanes ----------------
__global__ __launch_bounds__(256) void k_final(const float* __restrict__ bo,
                                               float* __restrict__ Out) {
    int v = (blockIdx.x * 256 + threadIdx.x) >> 5;
    if (v >= NN) return;
    int lane = threadIdx.x & 31;
    int col = lane * 2;
    int s = g_rs[v], e = g_rs[v + 1];
    float2 a0 = make_float2(0.f, 0.f), a1 = a0, a2 = a0, a3 = a0;
    int j = s;
    for (; j + 4 <= e; j += 4) {
        int s0 = __ldg(&g_perm[j]), s1 = __ldg(&g_perm[j + 1]);
        int s2 = __ldg(&g_perm[j + 2]), s3 = __ldg(&g_perm[j + 3]);
        float2 v0 = __ldg((const float2*)&g_z[s0 * 64 + col]);
        float2 v1 = __ldg((const float2*)&g_z[s1 * 64 + col]);
        float2 v2 = __ldg((const float2*)&g_z[s2 * 64 + col]);
        float2 v3 = __ldg((const float2*)&g_z[s3 * 64 + col]);
        a0.x += v0.x; a0.y += v0.y;
        a1.x += v1.x; a1.y += v1.y;
        a2.x += v2.x; a2.y += v2.y;
        a3.x += v3.x; a3.y += v3.y;
    }
    for (; j < e; j++) {
        float2 v0 = __ldg((const float2*)&g_z[__ldg(&g_perm[j]) * 64 + col]);
        a0.x += v0.x; a0.y += v0.y;
    }
    float2 bb = __ldg((const float2*)&bo[col]);
    Out[v * 64 + col + 0] = (a0.x + a1.x) + (a2.x + a3.x) + bb.x;
    Out[v * 64 + col + 1] = (a0.y + a1.y) + (a2.y + a3.y) + bb.y;
}

// ---------------- host ----------------
extern "C" void kernel_launch(void* const* d_in, const int* in_sizes, int n_in,
                              void* d_out, int out_size) {
    const float* feats = (const float*)d_in[0];
    const int*   src   = (const int*)d_in[1];
    const int*   dst   = (const int*)d_in[2];
    const float* W0    = (const float*)d_in[3];
    const float* b0    = (const float*)d_in[4];
    const float* W1    = (const float*)d_in[5];
    const float* b1    = (const float*)d_in[6];
    const float* W2    = (const float*)d_in[7];
    const float* b2    = (const float*)d_in[8];
    const float* Wo    = (const float*)d_in[9];
    const float* bo    = (const float*)d_in[10];
    float* out = (float*)d_out;

    void *p_indeg, *p_outdeg, *p_h, *p_y, *p_z;
    cudaGetSymbolAddress(&p_indeg, g_indeg);
    cudaGetSymbolAddress(&p_outdeg, g_outdeg);
    cudaGetSymbolAddress(&p_h, g_h);
    cudaGetSymbolAddress(&p_y, g_y);
    cudaGetSymbolAddress(&p_z, g_z);
    float* hbuf = (float*)p_h;
    __nv_bfloat162* ybuf = (__nv_bfloat162*)p_y;
    float* zbuf = (float*)p_z;

    cudaMemsetAsync(p_indeg, 0, NN * sizeof(int));
    cudaMemsetAsync(p_outdeg, 0, NN * sizeof(int));

    dim3 gconv((NN + 63) / 64, 2);
    int gz = (NN + 63) / 64;
    int ab = (NN * 32 + 255) / 256;
    int eb = (NE + 255) / 256;

    // fused: layer-1 GEMM (no onorm) + degree counting, one launch
    k_fused1<<<GB1 + DEGB, 256>>>(src, dst, feats, W0, ybuf);
    k_scan<<<1, 1024>>>();                     // scan + norms fused
    k_build<<<eb, 256>>>(src, dst);

    k_agg<<<ab, 256>>>(ybuf, b0, hbuf);
    k_gemm_conv_tc<<<gconv, 256>>>(hbuf, W1, ybuf);
    k_agg<<<ab, 256>>>(ybuf, b1, hbuf + (long long)NN * 128);
    k_gemm_conv_tc<<<gconv, 256>>>(hbuf + 1ll * NN * 128, W2, ybuf);
    k_agg<<<ab, 256>>>(ybuf, b2, hbuf + 2ll * NN * 128);
    k_gemm_z_tc<<<gz, 256>>>(hbuf, Wo, zbuf);
    k_final<<<ab, 256>>>(bo, out);
}